// round 10
// baseline (speedup 1.0000x reference)
#include <cuda_runtime.h>
#include <cstdint>

#define Bsz 128
#define Lseq 1024
#define Hd 256
#define G3 768
#define NBLK 256
#define HST 134   // u64 stride per h row (16B-aligned rows, conflict-free stagger)
#define WST 134   // u64 stride per weight row

typedef unsigned long long u64;

__device__ __forceinline__ u64 f2fma(u64 a, u64 b, u64 c) {
    u64 d; asm("fma.rn.f32x2 %0, %1, %2, %3;" : "=l"(d) : "l"(a), "l"(b), "l"(c)); return d;
}
__device__ __forceinline__ u64 f2add(u64 a, u64 b) {
    u64 d; asm("add.rn.f32x2 %0, %1, %2;" : "=l"(d) : "l"(a), "l"(b)); return d;
}
__device__ __forceinline__ u64 dup2(float x) {
    u64 r; asm("mov.b64 %0, {%1, %1};" : "=l"(r) : "f"(x)); return r;
}
__device__ __forceinline__ void up2(u64 v, float& lo, float& hi) {
    asm("mov.b64 {%0, %1}, %2;" : "=f"(lo), "=f"(hi) : "l"(v));
}
__device__ __forceinline__ float hsum2(u64 v) {
    float lo, hi; up2(v, lo, hi); return lo + hi;
}

// ---------------- scratch ----------------
__device__ float g_gi[(size_t)Lseq * G3 * Bsz];      // [t][3H][B] (layer-0 input gates)
__device__ float g_hseq0[(size_t)Lseq * Hd * Bsz];   // [t][k][b]
__device__ float g_hseq1[(size_t)Lseq * Hd * Bsz];

__device__ unsigned g_cnt[32];   // single global barrier (padded)
__device__ unsigned g_gen[32];

// ---------------- input-side GEMM (layer 0 only): Gi[t][c][b] ----------------
__global__ __launch_bounds__(256) void gi_gemm_kernel(
    const float* __restrict__ xin, const float* __restrict__ W,
    const float* __restrict__ bias)
{
    __shared__ float Ws[16 * 132];
    __shared__ float As[16 * 132];

    const int t  = blockIdx.y;
    const int c0 = blockIdx.x * 128;
    const int tid = threadIdx.x;
    const int ty = tid >> 4;
    const int tx = tid & 15;

    u64 acc2[8][4];
#pragma unroll
    for (int i = 0; i < 8; i++)
#pragma unroll
        for (int j = 0; j < 4; j++) acc2[i][j] = 0ull;

    for (int k0 = 0; k0 < 256; k0 += 16) {
        {
            int row  = tid >> 2;
            int col4 = (tid & 3) * 4;
#pragma unroll
            for (int it = 0; it < 2; it++, row += 64) {
                float4 w = *(const float4*)(W + (size_t)(c0 + row) * 256 + k0 + col4);
                Ws[(col4 + 0) * 132 + row] = w.x;
                Ws[(col4 + 1) * 132 + row] = w.y;
                Ws[(col4 + 2) * 132 + row] = w.z;
                Ws[(col4 + 3) * 132 + row] = w.w;
            }
        }
        {
            int row  = tid >> 2;
            int col4 = (tid & 3) * 4;
#pragma unroll
            for (int it = 0; it < 2; it++, row += 64) {
                float4 a = *(const float4*)(xin + ((size_t)row * Lseq + t) * 256 + k0 + col4);
                As[(col4 + 0) * 132 + row] = a.x;
                As[(col4 + 1) * 132 + row] = a.y;
                As[(col4 + 2) * 132 + row] = a.z;
                As[(col4 + 3) * 132 + row] = a.w;
            }
        }
        __syncthreads();

#pragma unroll
        for (int kk = 0; kk < 16; kk++) {
            float wr[8];
            *(float4*)(wr)     = *(const float4*)(Ws + kk * 132 + ty * 4);
            *(float4*)(wr + 4) = *(const float4*)(Ws + kk * 132 + 64 + ty * 4);
            ulonglong2 aA = *(const ulonglong2*)(As + kk * 132 + tx * 4);
            ulonglong2 aB = *(const ulonglong2*)(As + kk * 132 + 64 + tx * 4);
#pragma unroll
            for (int i = 0; i < 8; i++) {
                u64 wd = dup2(wr[i]);
                acc2[i][0] = f2fma(aA.x, wd, acc2[i][0]);
                acc2[i][1] = f2fma(aA.y, wd, acc2[i][1]);
                acc2[i][2] = f2fma(aB.x, wd, acc2[i][2]);
                acc2[i][3] = f2fma(aB.y, wd, acc2[i][3]);
            }
        }
        __syncthreads();
    }

    float* gout = g_gi + (size_t)t * G3 * Bsz;
#pragma unroll
    for (int i = 0; i < 8; i++) {
        int c = (i < 4) ? (c0 + ty * 4 + i) : (c0 + 64 + ty * 4 + (i - 4));
        float bv = bias[c];
        float a0, a1, a2, a3, a4, a5, a6, a7;
        up2(acc2[i][0], a0, a1); up2(acc2[i][1], a2, a3);
        up2(acc2[i][2], a4, a5); up2(acc2[i][3], a6, a7);
        *(float4*)(gout + (size_t)c * Bsz + tx * 4) =
            make_float4(a0 + bv, a1 + bv, a2 + bv, a3 + bv);
        *(float4*)(gout + (size_t)c * Bsz + 64 + tx * 4) =
            make_float4(a4 + bv, a5 + bv, a6 + bv, a7 + bv);
    }
}

// ---------------- fused two-layer pipelined GRU recurrence ----------------
// 256 blocks x 512 threads (2/SM). Block tile: 16 b x 8 j, BOTH layers.
// Superstep s: layer0 computes t=s (if s<L), layer1 computes t=s-1 (if s>=1).
// Shared h0(s-1) stage feeds both L0's gh0 dot and L1's gi1 dot.
// 9 weight matrices (L0 hh r/z/n; L1 ih r/z/n; L1 hh r/z/n), k-paired f32x2.
// kq-split reduced via warp shuffles (no SMEM reduction, no extra syncs).
__global__ __launch_bounds__(512, 2) void gru_pipe_kernel(
    const float* __restrict__ w_hh0, const float* __restrict__ b_hh0,
    const float* __restrict__ w_ih1, const float* __restrict__ w_hh1,
    const float* __restrict__ b_ih1, const float* __restrict__ b_hh1,
    const float* __restrict__ h0all)
{
    extern __shared__ __align__(16) char smraw[];
    u64*   w9_s = (u64*)smraw;              // 72 rows * WST
    u64*   h0_s = w9_s + 72 * WST;          // 16 b * HST
    u64*   h1_s = h0_s + 16 * HST;          // 16 b * HST
    float* bb_s = (float*)(h1_s + 16 * HST);// 24 (L0 bhh) + 32 (L1) floats

    const int tid = threadIdx.x;
    const int bt = blockIdx.x >> 5;   // 0..7 -> 16 batches
    const int ht = blockIdx.x & 31;   // 0..31 -> 8 hidden
    const int b0 = bt * 16;
    const int j0 = ht * 8;

    // ---- stage 9 weight matrix slices, k-paired ----
    for (int idx = tid; idx < 72 * 128; idx += 512) {
        int row = idx >> 7;              // m*8 + jl
        int kp  = idx & 127;
        int m = row >> 3, jl = row & 7;
        int jg = j0 + jl;
        const float* src;
        if (m < 3)      src = w_hh0 + (size_t)(m * 256 + jg) * 256;
        else if (m < 6) src = w_ih1 + (size_t)((m - 3) * 256 + jg) * 256;
        else            src = w_hh1 + (size_t)((m - 6) * 256 + jg) * 256;
        w9_s[row * WST + kp] = *(const u64*)(src + 2 * kp);
    }
    if (tid < 8) {
        int jl = tid, jg = j0 + jl;
        bb_s[jl]      = b_hh0[jg];
        bb_s[8 + jl]  = b_hh0[256 + jg];
        bb_s[16 + jl] = b_hh0[512 + jg];
        bb_s[24 + jl] = b_ih1[jg] + b_hh1[jg];              // combined r
        bb_s[32 + jl] = b_ih1[256 + jg] + b_hh1[256 + jg];  // combined z
        bb_s[40 + jl] = b_ih1[512 + jg];                    // gi_n bias
        bb_s[48 + jl] = b_hh1[512 + jg];                    // gh_n bias
    }

    unsigned* cnt_p = &g_cnt[0];
    unsigned* gen_p = &g_gen[0];
    unsigned gen;
    asm volatile("ld.acquire.gpu.u32 %0, [%1];" : "=r"(gen) : "l"(gen_p) : "memory");

    // thread mapping: warp = 16 (jl 8 x halfb 2); lane = kq(4) x bq(8)
    const int warp = tid >> 5;
    const int jl   = warp >> 1;
    const int jg   = j0 + jl;
    const int lane = tid & 31;
    const int kq   = lane >> 3;
    const int b    = (warp & 1) * 8 + (lane & 7);   // 0..15
    const int kbase = kq * 32;                      // pair offset (64 k per kq)

    const u64* h0p = h0_s + b * HST + kbase;
    const u64* h1p = h1_s + b * HST + kbase;
    const u64* wbase = w9_s + jl * WST + kbase;     // + m*8*WST per matrix

    const size_t gidx = (size_t)jg * Bsz + b0 + b;
    float gir = 0.f, giz = 0.f, gin = 0.f;
    if (kq == 0) {
        gir = g_gi[gidx];
        giz = g_gi[32768 + gidx];
        gin = g_gi[65536 + gidx];
    }
    __syncthreads();

    for (int s = 0; s <= Lseq; s++) {
        // ---- stage h0(s-1) and h1(s-2), pair layout [b][k2] ----
        if (s == 0) {
            const float* h0i = h0all;                    // [b][k]
            for (int i = tid; i < 2048; i += 512) {
                int bl = i >> 7, k2 = i & 127;
                float2 v = *(const float2*)(h0i + (size_t)(b0 + bl) * 256 + 2 * k2);
                h0_s[bl * HST + k2] = *(const u64*)&v;
            }
        } else {
            const float* sp = g_hseq0 + (size_t)(s - 1) * 32768;
            for (int i = tid; i < 2048; i += 512) {
                int k2 = i >> 4, bl = i & 15;
                float lo = sp[(2 * k2) * 128 + b0 + bl];
                float hi = sp[(2 * k2 + 1) * 128 + b0 + bl];
                float2 v = make_float2(lo, hi);
                h0_s[bl * HST + k2] = *(const u64*)&v;
            }
        }
        if (s <= 1) {
            const float* h1i = h0all + (size_t)Bsz * Hd;  // layer-1 init, [b][k]
            for (int i = tid; i < 2048; i += 512) {
                int bl = i >> 7, k2 = i & 127;
                float2 v = *(const float2*)(h1i + (size_t)(b0 + bl) * 256 + 2 * k2);
                h1_s[bl * HST + k2] = *(const u64*)&v;
            }
        } else {
            const float* sp = g_hseq1 + (size_t)(s - 2) * 32768;
            for (int i = tid; i < 2048; i += 512) {
                int k2 = i >> 4, bl = i & 15;
                float lo = sp[(2 * k2) * 128 + b0 + bl];
                float hi = sp[(2 * k2 + 1) * 128 + b0 + bl];
                float2 v = make_float2(lo, hi);
                h1_s[bl * HST + k2] = *(const u64*)&v;
            }
        }
        __syncthreads();

        // ---- 9 dots over this thread's 64 k (32 pairs), f32x2 over k ----
        u64 acc[9];
#pragma unroll
        for (int m = 0; m < 9; m++) acc[m] = 0ull;
#pragma unroll
        for (int i = 0; i < 32; i += 2) {
            ulonglong2 hv0 = *(const ulonglong2*)(h0p + i);
            ulonglong2 hv1 = *(const ulonglong2*)(h1p + i);
#pragma unroll
            for (int m = 0; m < 9; m++) {
                ulonglong2 wv = *(const ulonglong2*)(wbase + m * (8 * WST) + i);
                u64 hx = (m < 6) ? hv0.x : hv1.x;
                u64 hy = (m < 6) ? hv0.y : hv1.y;
                acc[m] = f2fma(hx, wv.x, acc[m]);
                acc[m] = f2fma(hy, wv.y, acc[m]);
            }
        }

        // ---- reduce over kq (lane bits 3,4) via shuffles ----
#pragma unroll
        for (int m = 0; m < 9; m++) {
            acc[m] = f2add(acc[m], __shfl_xor_sync(0xffffffffu, acc[m], 8));
            acc[m] = f2add(acc[m], __shfl_xor_sync(0xffffffffu, acc[m], 16));
        }

        // ---- activations (kq==0 lanes store) ----
        if (kq == 0) {
            if (s < Lseq) {   // layer 0, t = s
                float gr = hsum2(acc[0]) + bb_s[jl];
                float gz = hsum2(acc[1]) + bb_s[8 + jl];
                float gn = hsum2(acc[2]) + bb_s[16 + jl];
                float r = 1.0f / (1.0f + __expf(-(gir + gr)));
                float z = 1.0f / (1.0f + __expf(-(giz + gz)));
                float n = tanhf(gin + r * gn);
                u64 hp = h0_s[b * HST + (jg >> 1)];
                float hl, hh; up2(hp, hl, hh);
                float hprev = (jg & 1) ? hh : hl;
                float hnew = (1.0f - z) * n + z * hprev;
                g_hseq0[(size_t)s * 32768 + (size_t)jg * 128 + b0 + b] = hnew;
            }
            if (s >= 1) {     // layer 1, t = s-1
                float A = hsum2(acc[3]) + hsum2(acc[6]) + bb_s[24 + jl];
                float B = hsum2(acc[4]) + hsum2(acc[7]) + bb_s[32 + jl];
                float C = hsum2(acc[5]) + bb_s[40 + jl];
                float D = hsum2(acc[8]) + bb_s[48 + jl];
                float r1 = 1.0f / (1.0f + __expf(-A));
                float z1 = 1.0f / (1.0f + __expf(-B));
                float n1 = tanhf(C + r1 * D);
                u64 hp = h1_s[b * HST + (jg >> 1)];
                float hl, hh; up2(hp, hl, hh);
                float hprev = (jg & 1) ? hh : hl;
                float hnew = (1.0f - z1) * n1 + z1 * hprev;
                g_hseq1[(size_t)(s - 1) * 32768 + (size_t)jg * 128 + b0 + b] = hnew;
            }
        }
        __syncthreads();

        // ---- global barrier (skip after final superstep) ----
        if (s < Lseq) {
            unsigned target = gen + 1;
            if (tid == 0) {
                unsigned old;
                asm volatile("atom.release.gpu.add.u32 %0, [%1], %2;"
                             : "=r"(old) : "l"(cnt_p), "r"(1u) : "memory");
                if (old == NBLK - 1u) {
                    asm volatile("st.relaxed.gpu.u32 [%0], %1;" :: "l"(cnt_p), "r"(0u) : "memory");
                    asm volatile("st.release.gpu.u32 [%0], %1;" :: "l"(gen_p), "r"(target) : "memory");
                }
            }
            if (kq == 0 && s + 1 < Lseq) {   // prefetch gi for L0 t=s+1
                const float* gp = g_gi + (size_t)(s + 1) * (G3 * Bsz);
                gir = gp[gidx];
                giz = gp[32768 + gidx];
                gin = gp[65536 + gidx];
            }
            if (tid == 0) {
                unsigned v;
                do {
                    asm volatile("ld.acquire.gpu.u32 %0, [%1];" : "=r"(v) : "l"(gen_p) : "memory");
                } while (v != target);
            }
            gen = target;
            __syncthreads();
        }
    }
}

// ---------------- transpose g_hseq1 [t][h][b] -> out [b][t][h] ----------------
__global__ __launch_bounds__(256) void transpose_out_kernel(float* __restrict__ out)
{
    __shared__ float tile[32 * 129];
    const int t  = blockIdx.y;
    const int h0 = blockIdx.x * 32;
    const int tid = threadIdx.x;
    const float* src = g_hseq1 + (size_t)t * (Hd * Bsz) + (size_t)h0 * Bsz;

    for (int idx = tid; idx < 4096; idx += 256) {
        int hh = idx >> 7, bb = idx & 127;
        tile[hh * 129 + bb] = src[idx];
    }
    __syncthreads();
    for (int idx = tid; idx < 4096; idx += 256) {
        int bb = idx >> 5, hh = idx & 31;
        out[(size_t)bb * Lseq * Hd + (size_t)t * Hd + h0 + hh] = tile[hh * 129 + bb];
    }
}

// ---------------- final hidden states ----------------
__global__ __launch_bounds__(256) void hn_kernel(float* __restrict__ out)
{
    int idx = blockIdx.x * blockDim.x + threadIdx.x;  // 0..65535
    int layer = idx >> 15;
    int b = (idx >> 8) & 127;
    int h = idx & 255;
    const float* hs = layer ? g_hseq1 : g_hseq0;
    out[(size_t)Bsz * Lseq * Hd + idx] =
        hs[(size_t)(Lseq - 1) * (Hd * Bsz) + (size_t)h * Bsz + b];
}

// ---------------- launcher ----------------
extern "C" void kernel_launch(void* const* d_in, const int* in_sizes, int n_in,
                              void* d_out, int out_size)
{
    const float* x     = (const float*)d_in[0];
    const float* h0    = (const float*)d_in[1];
    const float* w_ih0 = (const float*)d_in[2];
    const float* w_hh0 = (const float*)d_in[3];
    const float* b_ih0 = (const float*)d_in[4];
    const float* b_hh0 = (const float*)d_in[5];
    const float* w_ih1 = (const float*)d_in[6];
    const float* w_hh1 = (const float*)d_in[7];
    const float* b_ih1 = (const float*)d_in[8];
    const float* b_hh1 = (const float*)d_in[9];
    float* out = (float*)d_out;

    const size_t smem = (size_t)(72 * WST + 2 * 16 * HST) * sizeof(u64)
                      + 64 * sizeof(float);   // ~109.3 KB
    cudaFuncSetAttribute(gru_pipe_kernel,
                         cudaFuncAttributeMaxDynamicSharedMemorySize, (int)smem);

    gi_gemm_kernel<<<dim3(6, Lseq), 256>>>(x, w_ih0, b_ih0);
    gru_pipe_kernel<<<NBLK, 512, smem>>>(w_hh0, b_hh0, w_ih1, w_hh1, b_ih1, b_hh1, h0);
    transpose_out_kernel<<<dim3(8, Lseq), 256>>>(out);
    if (out_size >= (int)((size_t)Bsz * Lseq * Hd + 2 * Bsz * Hd))
        hn_kernel<<<256, 256>>>(out);
}

// round 11
// speedup vs baseline: 1.5643x; 1.5643x over previous
#include <cuda_runtime.h>
#include <cstdint>

#define Bsz 128
#define Lseq 1024
#define Hd 256
#define G3 768
#define RBLK 128
#define W2S 258   // u64 stride per duplicated-weight row

typedef unsigned long long u64;

__device__ __forceinline__ u64 f2fma(u64 a, u64 b, u64 c) {
    u64 d; asm("fma.rn.f32x2 %0, %1, %2, %3;" : "=l"(d) : "l"(a), "l"(b), "l"(c)); return d;
}
__device__ __forceinline__ u64 f2add(u64 a, u64 b) {
    u64 d; asm("add.rn.f32x2 %0, %1, %2;" : "=l"(d) : "l"(a), "l"(b)); return d;
}
__device__ __forceinline__ u64 dup2(float x) {
    u64 r; asm("mov.b64 %0, {%1, %1};" : "=l"(r) : "f"(x)); return r;
}
__device__ __forceinline__ void up2(u64 v, float& lo, float& hi) {
    asm("mov.b64 {%0, %1}, %2;" : "=f"(lo), "=f"(hi) : "l"(v));
}

// ---------------- scratch ----------------
__device__ float g_gi[(size_t)Lseq * G3 * Bsz];      // [t][3H][B]
__device__ float g_hseq0[(size_t)Lseq * Hd * Bsz];   // [t][k][b]
__device__ float g_hseq1[(size_t)Lseq * Hd * Bsz];

// per-producer progress flags: [bt(4)][ht(32)], 128B-strided
__device__ unsigned g_flag[4 * 32 * 32];
// single init barrier
__device__ unsigned g_cnt[32];
__device__ unsigned g_gen[32];

// ---------------- input-side GEMM: Gi[t][c][b] ----------------
__global__ __launch_bounds__(256) void gi_gemm_kernel(
    const float* __restrict__ xin, const float* __restrict__ W,
    const float* __restrict__ bias, int layer)
{
    __shared__ float Ws[16 * 132];
    __shared__ float As[16 * 132];

    const int t  = blockIdx.y;
    const int c0 = blockIdx.x * 128;
    const int tid = threadIdx.x;
    const int ty = tid >> 4;
    const int tx = tid & 15;

    u64 acc2[8][4];
#pragma unroll
    for (int i = 0; i < 8; i++)
#pragma unroll
        for (int j = 0; j < 4; j++) acc2[i][j] = 0ull;

    for (int k0 = 0; k0 < 256; k0 += 16) {
        {
            int row  = tid >> 2;
            int col4 = (tid & 3) * 4;
#pragma unroll
            for (int it = 0; it < 2; it++, row += 64) {
                float4 w = *(const float4*)(W + (size_t)(c0 + row) * 256 + k0 + col4);
                Ws[(col4 + 0) * 132 + row] = w.x;
                Ws[(col4 + 1) * 132 + row] = w.y;
                Ws[(col4 + 2) * 132 + row] = w.z;
                Ws[(col4 + 3) * 132 + row] = w.w;
            }
        }
        if (layer == 0) {
            int row  = tid >> 2;
            int col4 = (tid & 3) * 4;
#pragma unroll
            for (int it = 0; it < 2; it++, row += 64) {
                float4 a = *(const float4*)(xin + ((size_t)row * Lseq + t) * 256 + k0 + col4);
                As[(col4 + 0) * 132 + row] = a.x;
                As[(col4 + 1) * 132 + row] = a.y;
                As[(col4 + 2) * 132 + row] = a.z;
                As[(col4 + 3) * 132 + row] = a.w;
            }
        } else {
#pragma unroll
            for (int it = 0; it < 2; it++) {
                int idx = tid + it * 256;
                int k  = idx >> 5;
                int b4 = (idx & 31) * 4;
                float4 a = *(const float4*)(g_hseq0 + ((size_t)t * 256 + k0 + k) * 128 + b4);
                *(float4*)(As + k * 132 + b4) = a;
            }
        }
        __syncthreads();

#pragma unroll
        for (int kk = 0; kk < 16; kk++) {
            float wr[8];
            *(float4*)(wr)     = *(const float4*)(Ws + kk * 132 + ty * 4);
            *(float4*)(wr + 4) = *(const float4*)(Ws + kk * 132 + 64 + ty * 4);
            ulonglong2 aA = *(const ulonglong2*)(As + kk * 132 + tx * 4);
            ulonglong2 aB = *(const ulonglong2*)(As + kk * 132 + 64 + tx * 4);
#pragma unroll
            for (int i = 0; i < 8; i++) {
                u64 wd = dup2(wr[i]);
                acc2[i][0] = f2fma(aA.x, wd, acc2[i][0]);
                acc2[i][1] = f2fma(aA.y, wd, acc2[i][1]);
                acc2[i][2] = f2fma(aB.x, wd, acc2[i][2]);
                acc2[i][3] = f2fma(aB.y, wd, acc2[i][3]);
            }
        }
        __syncthreads();
    }

    float* gout = g_gi + (size_t)t * G3 * Bsz;
#pragma unroll
    for (int i = 0; i < 8; i++) {
        int c = (i < 4) ? (c0 + ty * 4 + i) : (c0 + 64 + ty * 4 + (i - 4));
        float bv = bias[c];
        float a0, a1, a2, a3, a4, a5, a6, a7;
        up2(acc2[i][0], a0, a1); up2(acc2[i][1], a2, a3);
        up2(acc2[i][2], a4, a5); up2(acc2[i][3], a6, a7);
        *(float4*)(gout + (size_t)c * Bsz + tx * 4) =
            make_float4(a0 + bv, a1 + bv, a2 + bv, a3 + bv);
        *(float4*)(gout + (size_t)c * Bsz + 64 + tx * 4) =
            make_float4(a4 + bv, a5 + bv, a6 + bv, a7 + bv);
    }
}

// ---------------- persistent GRU recurrence: dataflow version ----------------
// 128 blocks x 512 threads. Block tile: 32 b x 8 j (R4 shape).
// NO per-step grid barrier: producer (bt,ht) publishes its 8-j chunk of h(t)
// with flag g_flag[bt][ht]=t+1; consumers stage chunks into SMEM as they
// arrive (warp w stages 2 chunks), dot threads spin on per-chunk SMEM flags.
__global__ __launch_bounds__(512) void gru_recur_kernel(
    const float* __restrict__ w_hh, const float* __restrict__ b_hh,
    const float* __restrict__ h0all, int layer)
{
    extern __shared__ __align__(16) char smraw[];
    u64*   w2_s  = (u64*)smraw;            // 24*258 = 6192 u64
    u64*   red_s = w2_s + 6192;            // 8 kq * 384 = 3072 u64
    float* h_s   = (float*)(red_s + 3072); // 256 k * 32 b = 8192 floats
    float* red2  = h_s + 8192;             // 768 floats
    float* bh_s  = red2 + 768;             // 24 floats (+pad to 32)
    volatile unsigned* smflag = (volatile unsigned*)(bh_s + 32);  // 32 chunk flags

    const int tid = threadIdx.x;
    const int bt = blockIdx.x >> 5;
    const int ht = blockIdx.x & 31;
    const int b0 = bt * 32;
    const int j0 = ht * 8;

    float* hseq = layer ? g_hseq1 : g_hseq0;
    unsigned* myflag = &g_flag[(bt * 32 + ht) * 32];

    // reset my flag + smem flags (visible to group via init barrier below)
    if (tid == 0)
        asm volatile("st.relaxed.gpu.u32 [%0], %1;" :: "l"(myflag), "r"(0u) : "memory");
    if (tid < 32) smflag[tid] = 0u;

    // duplicated persistent weights
    for (int idx = tid; idx < 6144; idx += 512) {
        int gj = idx >> 8;
        int k  = idx & 255;
        int g  = gj >> 3, j = gj & 7;
        w2_s[gj * W2S + k] = dup2(__ldg(w_hh + (size_t)(g * 256 + j0 + j) * 256 + k));
    }
    if (tid < 24) {
        int g = tid >> 3, j = tid & 7;
        bh_s[tid] = b_hh[g * 256 + j0 + j];
    }
    __syncthreads();

    // ---- one init barrier: all flag resets visible before any polling ----
    {
        unsigned gen;
        asm volatile("ld.acquire.gpu.u32 %0, [%1];" : "=r"(gen) : "l"(&g_gen[0]) : "memory");
        unsigned target = gen + 1;
        if (tid == 0) {
            unsigned old;
            asm volatile("atom.release.gpu.add.u32 %0, [%1], %2;"
                         : "=r"(old) : "l"(&g_cnt[0]), "r"(1u) : "memory");
            if (old == RBLK - 1u) {
                asm volatile("st.relaxed.gpu.u32 [%0], %1;" :: "l"(&g_cnt[0]), "r"(0u) : "memory");
                asm volatile("st.release.gpu.u32 [%0], %1;" :: "l"(&g_gen[0]), "r"(target) : "memory");
            }
            unsigned v;
            do {
                asm volatile("ld.acquire.gpu.u32 %0, [%1];" : "=r"(v) : "l"(&g_gen[0]) : "memory");
            } while (v < target);
        }
        __syncthreads();
    }

    const int bq = tid & 7;
    const int j  = (tid >> 3) & 7;
    const int kq = tid >> 6;
    const int kbase = kq * 32;
    const int warp = tid >> 5;
    const int lane = tid & 31;

    const u64* wrp = w2_s + (0 + j) * W2S + kbase;
    const u64* wzp = w2_s + (8 + j) * W2S + kbase;
    const u64* wnp = w2_s + (16 + j) * W2S + kbase;
    const float* hb = h_s + kbase * 32 + bq * 4;

    // activation-thread mapping (tid < 256)
    const int ab = tid & 31;
    const int aj = (tid >> 5) & 7;
    const size_t gidx = (size_t)(j0 + aj) * Bsz + b0 + ab;

    float cir = 0.f, ciz = 0.f, cin_ = 0.f;
    if (tid < 256) {
        cir  = __ldg(g_gi + gidx);
        ciz  = __ldg(g_gi + 32768 + gidx);
        cin_ = __ldg(g_gi + 65536 + gidx);
    }

    for (int t = 0; t < Lseq; t++) {
        // ---- phase A: stage h(t-1) chunks into h_s as they arrive ----
        if (t == 0) {
            const float* h0g = h0all + (size_t)layer * Bsz * Hd;  // [b][k]
            for (int i = tid; i < 8192; i += 512) {
                int k = i >> 5, bb = i & 31;
                h_s[k * 32 + bb] = h0g[(size_t)(b0 + bb) * 256 + k];
            }
            __syncthreads();
        } else {
            const float* src = hseq + (size_t)(t - 1) * (Hd * Bsz);
            const int kq_w = warp >> 1;
#pragma unroll
            for (int e = 0; e < 2; e++) {
                int c = kq_w * 4 + (warp & 1) * 2 + e;
                const unsigned* fp = &g_flag[(bt * 32 + c) * 32];
                unsigned v;
                do {
                    asm volatile("ld.acquire.gpu.u32 %0, [%1];" : "=r"(v) : "l"(fp) : "memory");
                } while (v < (unsigned)t);
                int k   = c * 8 + (lane >> 2);
                int col = (lane & 3) * 4;
                const float* sp = src + (size_t)k * Bsz + b0;
                float4 v0 = *(const float4*)(sp + col);
                float4 v1 = *(const float4*)(sp + col + 16);
                *(float4*)(h_s + k * 32 + col)      = v0;
                *(float4*)(h_s + k * 32 + col + 16) = v1;
                __syncwarp();
                __threadfence_block();
                if (lane == 0) smflag[c] = (unsigned)t;
            }
            // wait for all 4 chunks this thread's dot needs
#pragma unroll
            for (int e = 0; e < 4; e++) {
                int c = kq * 4 + e;
                while (smflag[c] < (unsigned)t) { }
            }
            __threadfence_block();
        }

        // ---- partial dot over this thread's 32 k (f32x2 over batch) ----
        u64 ar0 = 0, ar1 = 0, az0 = 0, az1 = 0, an0 = 0, an1 = 0;
#pragma unroll
        for (int i = 0; i < 32; i += 2) {
            ulonglong2 ha = *(const ulonglong2*)(hb + i * 32);
            ulonglong2 hc = *(const ulonglong2*)(hb + i * 32 + 32);
            ulonglong2 wr = *(const ulonglong2*)(wrp + i);
            ulonglong2 wz = *(const ulonglong2*)(wzp + i);
            ulonglong2 wn = *(const ulonglong2*)(wnp + i);
            ar0 = f2fma(ha.x, wr.x, ar0); ar1 = f2fma(ha.y, wr.x, ar1);
            ar0 = f2fma(hc.x, wr.y, ar0); ar1 = f2fma(hc.y, wr.y, ar1);
            az0 = f2fma(ha.x, wz.x, az0); az1 = f2fma(ha.y, wz.x, az1);
            az0 = f2fma(hc.x, wz.y, az0); az1 = f2fma(hc.y, wz.y, az1);
            an0 = f2fma(ha.x, wn.x, an0); an1 = f2fma(ha.y, wn.x, an1);
            an0 = f2fma(hc.x, wn.y, an0); an1 = f2fma(hc.y, wn.y, an1);
        }
        {
            u64* rb = red_s + (size_t)kq * 384 + (j * 8 + bq) * 2;
            *(ulonglong2*)(rb)       = make_ulonglong2(ar0, ar1);
            *(ulonglong2*)(rb + 128) = make_ulonglong2(az0, az1);
            *(ulonglong2*)(rb + 256) = make_ulonglong2(an0, an1);
        }
        __syncthreads();

        // ---- reduce over kq: 192 threads ----
        if (tid < 192) {
            u64 s0 = 0, s1 = 0;
            const u64* base = red_s + tid * 2;
#pragma unroll
            for (int q = 0; q < 8; q++) {
                ulonglong2 v = *(const ulonglong2*)(base + q * 384);
                s0 = f2add(s0, v.x);
                s1 = f2add(s1, v.y);
            }
            int g = tid >> 6, jj = (tid >> 3) & 7, bb = tid & 7;
            float l0, h0f, l1, h1f;
            up2(s0, l0, h0f); up2(s1, l1, h1f);
            *(float4*)(red2 + (g * 8 + jj) * 32 + bb * 4) = make_float4(l0, h0f, l1, h1f);
        }
        __syncthreads();

        // ---- activation + publish hnew: 256 threads ----
        if (tid < 256) {
            float gr = red2[aj * 32 + ab]        + bh_s[aj];
            float gz = red2[(8 + aj) * 32 + ab]  + bh_s[8 + aj];
            float gn = red2[(16 + aj) * 32 + ab] + bh_s[16 + aj];
            float r = 1.0f / (1.0f + __expf(-(cir + gr)));
            float z = 1.0f / (1.0f + __expf(-(ciz + gz)));
            float n = tanhf(cin_ + r * gn);
            float hprev = h_s[(j0 + aj) * 32 + ab];
            float hnew = (1.0f - z) * n + z * hprev;
            hseq[(size_t)t * (Hd * Bsz) + (size_t)(j0 + aj) * Bsz + b0 + ab] = hnew;
        }
        __syncthreads();   // stores done + all h_s reads done (before restaging)

        if (tid == 0) {
            asm volatile("st.release.gpu.u32 [%0], %1;"
                         :: "l"(myflag), "r"((unsigned)(t + 1)) : "memory");
        }
        // prefetch next-step gi (off critical path)
        if (tid < 256 && t + 1 < Lseq) {
            const float* gi_n = g_gi + (size_t)(t + 1) * (G3 * Bsz);
            cir  = __ldg(gi_n + gidx);
            ciz  = __ldg(gi_n + 32768 + gidx);
            cin_ = __ldg(gi_n + 65536 + gidx);
        }
    }
}

// ---------------- transpose g_hseq1 [t][h][b] -> out [b][t][h] ----------------
__global__ __launch_bounds__(256) void transpose_out_kernel(float* __restrict__ out)
{
    __shared__ float tile[32 * 129];
    const int t  = blockIdx.y;
    const int h0 = blockIdx.x * 32;
    const int tid = threadIdx.x;
    const float* src = g_hseq1 + (size_t)t * (Hd * Bsz) + (size_t)h0 * Bsz;

    for (int idx = tid; idx < 4096; idx += 256) {
        int hh = idx >> 7, bb = idx & 127;
        tile[hh * 129 + bb] = src[idx];
    }
    __syncthreads();
    for (int idx = tid; idx < 4096; idx += 256) {
        int bb = idx >> 5, hh = idx & 31;
        out[(size_t)bb * Lseq * Hd + (size_t)t * Hd + h0 + hh] = tile[hh * 129 + bb];
    }
}

// ---------------- final hidden states ----------------
__global__ __launch_bounds__(256) void hn_kernel(float* __restrict__ out)
{
    int idx = blockIdx.x * blockDim.x + threadIdx.x;  // 0..65535
    int layer = idx >> 15;
    int b = (idx >> 8) & 127;
    int h = idx & 255;
    const float* hs = layer ? g_hseq1 : g_hseq0;
    out[(size_t)Bsz * Lseq * Hd + idx] =
        hs[(size_t)(Lseq - 1) * (Hd * Bsz) + (size_t)h * Bsz + b];
}

// ---------------- launcher ----------------
extern "C" void kernel_launch(void* const* d_in, const int* in_sizes, int n_in,
                              void* d_out, int out_size)
{
    const float* x     = (const float*)d_in[0];
    const float* h0    = (const float*)d_in[1];
    const float* w_ih0 = (const float*)d_in[2];
    const float* w_hh0 = (const float*)d_in[3];
    const float* b_ih0 = (const float*)d_in[4];
    const float* b_hh0 = (const float*)d_in[5];
    const float* w_ih1 = (const float*)d_in[6];
    const float* w_hh1 = (const float*)d_in[7];
    const float* b_ih1 = (const float*)d_in[8];
    const float* b_hh1 = (const float*)d_in[9];
    float* out = (float*)d_out;

    const size_t smem = (6192 + 3072) * sizeof(u64)
                      + (8192 + 768 + 32) * sizeof(float)
                      + 32 * sizeof(unsigned);
    cudaFuncSetAttribute(gru_recur_kernel,
                         cudaFuncAttributeMaxDynamicSharedMemorySize, (int)smem);

    gi_gemm_kernel<<<dim3(6, Lseq), 256>>>(x, w_ih0, b_ih0, 0);
    gru_recur_kernel<<<RBLK, 512, smem>>>(w_hh0, b_hh0, h0, 0);
    gi_gemm_kernel<<<dim3(6, Lseq), 256>>>(x, w_ih1, b_ih1, 1);
    gru_recur_kernel<<<RBLK, 512, smem>>>(w_hh1, b_hh1, h0, 1);
    transpose_out_kernel<<<dim3(8, Lseq), 256>>>(out);
    if (out_size >= (int)((size_t)Bsz * Lseq * Hd + 2 * Bsz * Hd))
        hn_kernel<<<256, 256>>>(out);
}